// round 4
// baseline (speedup 1.0000x reference)
#include <cuda_runtime.h>
#include <math.h>

// ---------------- problem dims (fixed) ----------------
#define BB   2
#define SS   2048
#define DD   768
#define HH   12
#define DK   64
#define FF   3072
#define MM   (BB*SS)          // 4096 tokens

// ---------------- scratch (device globals; allocation-free) ----------------
__device__ float g_h[MM*DD];            // LN1 output
__device__ float g_q[BB*HH*SS*DK];      // [B*H, S, DK]
__device__ float g_k[BB*HH*SS*DK];
__device__ float g_v[BB*HH*SS*DK];
__device__ float g_o[MM*DD];            // attn output, heads concatenated
__device__ float g_y[MM*DD];            // after O-proj + residual
__device__ float g_z[MM*DD];            // LN2 output
__device__ float g_u[MM*FF];            // FFN hidden

// ---------------- LayerNorm: one block per row (D=768, 256 threads) -------
__global__ void __launch_bounds__(256) ln_kernel(
    const float* __restrict__ x, const float* __restrict__ gw,
    const float* __restrict__ bw, float* __restrict__ out)
{
    int row = blockIdx.x;
    int tid = threadIdx.x;
    const float* xr = x + (size_t)row * DD;

    float v0 = xr[tid], v1 = xr[tid + 256], v2 = xr[tid + 512];
    float s = v0 + v1 + v2;

    __shared__ float red[8];
    #pragma unroll
    for (int o = 16; o > 0; o >>= 1) s += __shfl_xor_sync(0xffffffffu, s, o);
    if ((tid & 31) == 0) red[tid >> 5] = s;
    __syncthreads();
    float tot = red[0]+red[1]+red[2]+red[3]+red[4]+red[5]+red[6]+red[7];
    float mu = tot * (1.0f / 768.0f);

    float d0 = v0 - mu, d1 = v1 - mu, d2 = v2 - mu;
    float q = d0*d0 + d1*d1 + d2*d2;
    #pragma unroll
    for (int o = 16; o > 0; o >>= 1) q += __shfl_xor_sync(0xffffffffu, q, o);
    __syncthreads();
    if ((tid & 31) == 0) red[tid >> 5] = q;
    __syncthreads();
    float vtot = red[0]+red[1]+red[2]+red[3]+red[4]+red[5]+red[6]+red[7];
    float rstd = rsqrtf(vtot * (1.0f / 768.0f) + 1e-5f);

    float* orow = out + (size_t)row * DD;
    orow[tid]       = d0 * rstd * gw[tid]       + bw[tid];
    orow[tid + 256] = d1 * rstd * gw[tid + 256] + bw[tid + 256];
    orow[tid + 512] = d2 * rstd * gw[tid + 512] + bw[tid + 512];
}

// ---------------- generic SGEMM: C[M,N] = A[M,K] @ B + epilogue -----------
// Tile: 128(M) x 64(N), BK=16. 256 threads (16x16), 8x4 micro-tile per thread.
// HEADB: B is [H, K, 64] per-head weights, BN tile == one head.
// BHSK : output written as [B, H, S, DK] instead of [M, N].
template<bool HEADB, bool BHSK, bool BIAS, bool RES, bool GELU>
__global__ void __launch_bounds__(256) gemm_kernel(
    const float* __restrict__ A, const float* __restrict__ Bw,
    const float* __restrict__ bias, const float* __restrict__ res,
    float* __restrict__ C, int M, int N, int K)
{
    __shared__ float As[16][132];   // k-major, padded (f4-aligned reads)
    __shared__ float Bs[16][64];

    int tid = threadIdx.x;
    int tx = tid & 15, ty = tid >> 4;
    int bn = blockIdx.x, bm = blockIdx.y;
    int row0 = bm * 128;

    const float* Bp;
    int ldb, col0;
    if (HEADB) { Bp = Bw + (size_t)bn * K * 64; ldb = 64; col0 = 0; }
    else       { Bp = Bw;                        ldb = N;  col0 = bn * 64; }
    const float* Ap = A + (size_t)row0 * K;

    float acc[8][4];
    #pragma unroll
    for (int i = 0; i < 8; i++)
        #pragma unroll
        for (int j = 0; j < 4; j++) acc[i][j] = 0.0f;

    for (int k0 = 0; k0 < K; k0 += 16) {
        // stage A (128x16) transposed into smem
        #pragma unroll
        for (int l = 0; l < 2; l++) {
            int idx = (tid + l * 256) * 4;
            int r  = idx >> 4;
            int kk = idx & 15;
            float4 va = *(const float4*)(Ap + (size_t)r * K + k0 + kk);
            As[kk + 0][r] = va.x; As[kk + 1][r] = va.y;
            As[kk + 2][r] = va.z; As[kk + 3][r] = va.w;
        }
        // stage B (16x64)
        {
            int idx = tid * 4;
            int kr = idx >> 6;
            int c  = idx & 63;
            float4 vb = *(const float4*)(Bp + (size_t)(k0 + kr) * ldb + col0 + c);
            *(float4*)&Bs[kr][c] = vb;
        }
        __syncthreads();

        #pragma unroll
        for (int kk = 0; kk < 16; kk++) {
            float4 a0 = *(const float4*)&As[kk][ty * 8];
            float4 a1 = *(const float4*)&As[kk][ty * 8 + 4];
            float4 bq = *(const float4*)&Bs[kk][tx * 4];
            float a[8] = {a0.x, a0.y, a0.z, a0.w, a1.x, a1.y, a1.z, a1.w};
            float b[4] = {bq.x, bq.y, bq.z, bq.w};
            #pragma unroll
            for (int i = 0; i < 8; i++)
                #pragma unroll
                for (int j = 0; j < 4; j++)
                    acc[i][j] = fmaf(a[i], b[j], acc[i][j]);
        }
        __syncthreads();
    }

    // epilogue
    #pragma unroll
    for (int i = 0; i < 8; i++) {
        int r = row0 + ty * 8 + i;
        #pragma unroll
        for (int j = 0; j < 4; j++) {
            int c = bn * 64 + tx * 4 + j;      // global column
            float v = acc[i][j];
            if (BIAS) v += bias[c];
            if (GELU) v = 0.5f * v * (1.0f + erff(v * 0.70710678118654752f));
            if (RES)  v += res[(size_t)r * N + c];
            if (BHSK) {
                int b_  = r >> 11, s_ = r & 2047;
                int h_  = c >> 6,  k_ = c & 63;
                C[(((size_t)b_ * HH + h_) * SS + s_) * DK + k_] = v;
            } else {
                C[(size_t)r * N + c] = v;
            }
        }
    }
}

// ---------------- flash attention (fp32, non-causal) ----------------------
// grid (S/64, B*H), 256 threads (16x16), 4x4 micro-tile.
// smem: Qs,Ks k-major; Vs,Ps s-major; all rows padded to 68 floats.
#define APAD 68
#define ABUF (64 * APAD)
#define ATTN_SMEM (4 * ABUF * sizeof(float))

__global__ void __launch_bounds__(256) attn_kernel(
    const float* __restrict__ q, const float* __restrict__ k,
    const float* __restrict__ v, float* __restrict__ o)
{
    extern __shared__ float sm[];
    float* Qs = sm;               // Qs[kk*APAD + r]
    float* Ks = sm + ABUF;        // Ks[kk*APAD + c]
    float* Vs = sm + 2 * ABUF;    // Vs[s *APAD + d]
    float* Ps = sm + 3 * ABUF;    // Ps[s *APAD + r]

    int tid = threadIdx.x;
    int tx = tid & 15, ty = tid >> 4;
    int bh = blockIdx.y;
    int q0 = blockIdx.x * 64;

    const float* qb = q + ((size_t)bh * SS + q0) * DK;
    const float* kb = k + (size_t)bh * SS * DK;
    const float* vb = v + (size_t)bh * SS * DK;

    // load + pre-scale Q (once per block)
    #pragma unroll
    for (int l = 0; l < 4; l++) {
        int idx = (tid + l * 256) * 4;
        int r = idx >> 6, kk = idx & 63;
        float4 t = *(const float4*)(qb + (size_t)r * DK + kk);
        Qs[(kk + 0) * APAD + r] = t.x * 0.125f;
        Qs[(kk + 1) * APAD + r] = t.y * 0.125f;
        Qs[(kk + 2) * APAD + r] = t.z * 0.125f;
        Qs[(kk + 3) * APAD + r] = t.w * 0.125f;
    }

    float m_[4], l_[4], acc[4][4];
    #pragma unroll
    for (int i = 0; i < 4; i++) {
        m_[i] = -1e30f; l_[i] = 0.0f;
        #pragma unroll
        for (int j = 0; j < 4; j++) acc[i][j] = 0.0f;
    }

    for (int s0 = 0; s0 < SS; s0 += 64) {
        __syncthreads();   // protect Ks/Vs (prev iter readers) + Qs first time
        // K tile transposed (k-major)
        #pragma unroll
        for (int l = 0; l < 4; l++) {
            int idx = (tid + l * 256) * 4;
            int c = idx >> 6, kk = idx & 63;
            float4 t = *(const float4*)(kb + (size_t)(s0 + c) * DK + kk);
            Ks[(kk + 0) * APAD + c] = t.x;
            Ks[(kk + 1) * APAD + c] = t.y;
            Ks[(kk + 2) * APAD + c] = t.z;
            Ks[(kk + 3) * APAD + c] = t.w;
        }
        // V tile direct (s-major)
        #pragma unroll
        for (int l = 0; l < 4; l++) {
            int idx = (tid + l * 256) * 4;
            int s = idx >> 6, d = idx & 63;
            float4 t = *(const float4*)(vb + (size_t)(s0 + s) * DK + d);
            Vs[s * APAD + d + 0] = t.x;
            Vs[s * APAD + d + 1] = t.y;
            Vs[s * APAD + d + 2] = t.z;
            Vs[s * APAD + d + 3] = t.w;
        }
        __syncthreads();

        // S = Q @ K^T (pre-scaled)
        float sv[4][4];
        #pragma unroll
        for (int i = 0; i < 4; i++)
            #pragma unroll
            for (int j = 0; j < 4; j++) sv[i][j] = 0.0f;

        #pragma unroll 8
        for (int kk = 0; kk < 64; kk++) {
            float4 aq = *(const float4*)&Qs[kk * APAD + ty * 4];
            float4 bq = *(const float4*)&Ks[kk * APAD + tx * 4];
            float a[4] = {aq.x, aq.y, aq.z, aq.w};
            float b[4] = {bq.x, bq.y, bq.z, bq.w};
            #pragma unroll
            for (int i = 0; i < 4; i++)
                #pragma unroll
                for (int j = 0; j < 4; j++)
                    sv[i][j] = fmaf(a[i], b[j], sv[i][j]);
        }

        // online softmax (rows ty*4+i; reduce over 16 tx lanes)
        #pragma unroll
        for (int i = 0; i < 4; i++) {
            float rmax = fmaxf(fmaxf(sv[i][0], sv[i][1]), fmaxf(sv[i][2], sv[i][3]));
            #pragma unroll
            for (int off = 8; off > 0; off >>= 1)
                rmax = fmaxf(rmax, __shfl_xor_sync(0xffffffffu, rmax, off));
            float mn = fmaxf(m_[i], rmax);
            float al = __expf(m_[i] - mn);
            float rs = 0.0f;
            #pragma unroll
            for (int j = 0; j < 4; j++) {
                float p = __expf(sv[i][j] - mn);
                sv[i][j] = p; rs += p;
            }
            #pragma unroll
            for (int off = 8; off > 0; off >>= 1)
                rs += __shfl_xor_sync(0xffffffffu, rs, off);
            l_[i] = l_[i] * al + rs;
            m_[i] = mn;
            #pragma unroll
            for (int j = 0; j < 4; j++) acc[i][j] *= al;
            #pragma unroll
            for (int j = 0; j < 4; j++)
                Ps[(tx * 4 + j) * APAD + ty * 4 + i] = sv[i][j];
        }
        __syncthreads();

        // O += P @ V
        #pragma unroll 8
        for (int kk = 0; kk < 64; kk++) {
            float4 ap = *(const float4*)&Ps[kk * APAD + ty * 4];
            float4 bp = *(const float4*)&Vs[kk * APAD + tx * 4];
            float a[4] = {ap.x, ap.y, ap.z, ap.w};
            float b[4] = {bp.x, bp.y, bp.z, bp.w};
            #pragma unroll
            for (int i = 0; i < 4; i++)
                #pragma unroll
                for (int j = 0; j < 4; j++)
                    acc[i][j] = fmaf(a[i], b[j], acc[i][j]);
        }
    }

    // write O into concat-head layout [B, S, H*DK]
    int b_ = bh / HH, h_ = bh % HH;
    #pragma unroll
    for (int i = 0; i < 4; i++) {
        float inv = 1.0f / l_[i];
        size_t row = (size_t)b_ * SS + q0 + ty * 4 + i;
        #pragma unroll
        for (int j = 0; j < 4; j++)
            o[row * DD + h_ * DK + tx * 4 + j] = acc[i][j] * inv;
    }
}

// ---------------- launch ---------------------------------------------------
extern "C" void kernel_launch(void* const* d_in, const int* in_sizes, int n_in,
                              void* d_out, int out_size)
{
    (void)in_sizes; (void)n_in; (void)out_size;
    const float* x    = (const float*)d_in[0];
    const float* wq_w = (const float*)d_in[1];
    const float* wq_b = (const float*)d_in[2];
    const float* wk_w = (const float*)d_in[3];
    const float* wk_b = (const float*)d_in[4];
    const float* wv_w = (const float*)d_in[5];
    const float* wv_b = (const float*)d_in[6];
    const float* wo_w = (const float*)d_in[7];
    const float* wo_b = (const float*)d_in[8];
    const float* ln_g = (const float*)d_in[9];
    const float* ln_b = (const float*)d_in[10];
    const float* w1   = (const float*)d_in[11];
    const float* b1   = (const float*)d_in[12];
    const float* w2   = (const float*)d_in[13];
    const float* b2   = (const float*)d_in[14];
    float* out = (float*)d_out;

    float *h, *q, *k, *v, *o, *y, *z, *u;
    cudaGetSymbolAddress((void**)&h, g_h);
    cudaGetSymbolAddress((void**)&q, g_q);
    cudaGetSymbolAddress((void**)&k, g_k);
    cudaGetSymbolAddress((void**)&v, g_v);
    cudaGetSymbolAddress((void**)&o, g_o);
    cudaGetSymbolAddress((void**)&y, g_y);
    cudaGetSymbolAddress((void**)&z, g_z);
    cudaGetSymbolAddress((void**)&u, g_u);

    // 1) LN1
    ln_kernel<<<MM, 256>>>(x, ln_g, ln_b, h);

    // 2) QKV projections -> [B,H,S,DK]
    dim3 gp(DD / 64, MM / 128);   // (12, 32)
    gemm_kernel<true,  true,  true,  false, false><<<gp, 256>>>(h, wq_w, wq_b, nullptr, q, MM, DD, DD);
    gemm_kernel<true,  true,  true,  false, false><<<gp, 256>>>(h, wk_w, wk_b, nullptr, k, MM, DD, DD);
    gemm_kernel<true,  true,  true,  false, false><<<gp, 256>>>(h, wv_w, wv_b, nullptr, v, MM, DD, DD);

    // 3) attention
    cudaFuncSetAttribute(attn_kernel, cudaFuncAttributeMaxDynamicSharedMemorySize,
                         (int)ATTN_SMEM);
    attn_kernel<<<dim3(SS / 64, BB * HH), 256, ATTN_SMEM>>>(q, k, v, o);

    // 4) O-proj + bias + residual(x)
    gemm_kernel<false, false, true,  true,  false><<<gp, 256>>>(o, wo_w, wo_b, x, y, MM, DD, DD);

    // 5) LN2
    ln_kernel<<<MM, 256>>>(y, ln_g, ln_b, z);

    // 6) FFN1 + bias + exact GELU
    dim3 g1(FF / 64, MM / 128);   // (48, 32)
    gemm_kernel<false, false, true,  false, true ><<<g1, 256>>>(z, w1, b1, nullptr, u, MM, FF, DD);

    // 7) FFN2 + bias + residual(y) -> out
    gemm_kernel<false, false, true,  true,  false><<<gp, 256>>>(u, w2, b2, y, out, MM, DD, FF);
}

// round 7
// speedup vs baseline: 2.0901x; 2.0901x over previous
#include <cuda_runtime.h>
#include <math.h>
#include <cstdint>

// ---------------- problem dims (fixed) ----------------
#define BB   2
#define SS   2048
#define DD   768
#define HH   12
#define DK   64
#define FF   3072
#define MM   (BB*SS)          // 4096 tokens
#define NQKV (3*DD)           // 2304 fused QKV cols

// ---------------- scratch (device globals; allocation-free) ----------------
__device__ float g_h[MM*DD];            // LN1 output
__device__ float g_qkv[MM*NQKV];        // fused QKV [M, 2304]
__device__ float g_o[MM*DD];            // attn output, heads concatenated
__device__ float g_y[MM*DD];            // after O-proj + residual
__device__ float g_z[MM*DD];            // LN2 output
__device__ float g_u[MM*FF];            // FFN hidden
__device__ float g_wtq[NQKV*DD];        // transposed fused QKV weights [2304, 768]
__device__ float g_btq[NQKV];           // fused QKV bias
__device__ float g_wto[DD*DD];          // wo^T [768,768]
__device__ float g_wt1[FF*DD];          // w1^T [3072,768]
__device__ float g_wt2[DD*FF];          // w2^T [768,3072]

// ================= mma.sync helpers (portable ISA, sm_80+) =================
__device__ __forceinline__ uint32_t f2tf(float f) {
    uint32_t u; asm("cvt.rna.tf32.f32 %0, %1;" : "=r"(u) : "f"(f)); return u;
}
__device__ __forceinline__ void mma8(float* c, const uint32_t* a, const uint32_t* b) {
    asm volatile("mma.sync.aligned.m16n8k8.row.col.f32.tf32.tf32.f32 "
        "{%0,%1,%2,%3}, {%4,%5,%6,%7}, {%8,%9}, {%0,%1,%2,%3};"
        : "+f"(c[0]), "+f"(c[1]), "+f"(c[2]), "+f"(c[3])
        : "r"(a[0]), "r"(a[1]), "r"(a[2]), "r"(a[3]), "r"(b[0]), "r"(b[1]));
}
__device__ __forceinline__ float gelu_f(float v) {
    return 0.5f * v * (1.0f + erff(v * 0.70710678118654752f));
}

// ---------------- LayerNorm: one block per row (D=768, 256 threads) -------
__global__ void __launch_bounds__(256) ln_kernel(
    const float* __restrict__ x, const float* __restrict__ gw,
    const float* __restrict__ bw, float* __restrict__ out)
{
    int row = blockIdx.x;
    int tid = threadIdx.x;
    const float* xr = x + (size_t)row * DD;

    float v0 = xr[tid], v1 = xr[tid + 256], v2 = xr[tid + 512];
    float s = v0 + v1 + v2;

    __shared__ float red[8];
    #pragma unroll
    for (int o = 16; o > 0; o >>= 1) s += __shfl_xor_sync(0xffffffffu, s, o);
    if ((tid & 31) == 0) red[tid >> 5] = s;
    __syncthreads();
    float tot = red[0]+red[1]+red[2]+red[3]+red[4]+red[5]+red[6]+red[7];
    float mu = tot * (1.0f / 768.0f);

    float d0 = v0 - mu, d1 = v1 - mu, d2 = v2 - mu;
    float q = d0*d0 + d1*d1 + d2*d2;
    #pragma unroll
    for (int o = 16; o > 0; o >>= 1) q += __shfl_xor_sync(0xffffffffu, q, o);
    __syncthreads();
    if ((tid & 31) == 0) red[tid >> 5] = q;
    __syncthreads();
    float vtot = red[0]+red[1]+red[2]+red[3]+red[4]+red[5]+red[6]+red[7];
    float rstd = rsqrtf(vtot * (1.0f / 768.0f) + 1e-5f);

    float* orow = out + (size_t)row * DD;
    orow[tid]       = d0 * rstd * gw[tid]       + bw[tid];
    orow[tid + 256] = d1 * rstd * gw[tid + 256] + bw[tid + 256];
    orow[tid + 512] = d2 * rstd * gw[tid + 512] + bw[tid + 512];
}

// ---------------- weight transpose W[K,N] -> Wt[N,K] ----------------------
__global__ void __launch_bounds__(256) transpose_kernel(
    const float* __restrict__ W, float* __restrict__ Wt, int K, int N)
{
    __shared__ float t[32][33];
    int bx = blockIdx.x;  // n tile
    int by = blockIdx.y;  // k tile
    int tx = threadIdx.x, ty = threadIdx.y;  // (32, 8)
    #pragma unroll
    for (int l = 0; l < 4; l++) {
        int k = by * 32 + ty + l * 8;
        t[ty + l * 8][tx] = W[(size_t)k * N + bx * 32 + tx];
    }
    __syncthreads();
    #pragma unroll
    for (int l = 0; l < 4; l++) {
        int n = bx * 32 + ty + l * 8;
        Wt[(size_t)n * K + by * 32 + tx] = t[tx][ty + l * 8];
    }
}

// ---------------- QKV weight pack: [H,D,DK] x3 -> Wt [2304, 768] ----------
__global__ void __launch_bounds__(256) qkv_pack_kernel(
    const float* __restrict__ wq, const float* __restrict__ wk,
    const float* __restrict__ wv, float* __restrict__ wt)
{
    __shared__ float t[32][33];
    int p = blockIdx.z;                     // 0=q,1=k,2=v
    const float* wp = (p == 0) ? wq : (p == 1) ? wk : wv;
    int np0 = blockIdx.x * 32;              // col within part [0,768)
    int d0  = blockIdx.y * 32;
    int h   = np0 >> 6;
    int kk0 = np0 & 63;
    int tx = threadIdx.x, ty = threadIdx.y;
    #pragma unroll
    for (int l = 0; l < 4; l++) {
        int d = d0 + ty + l * 8;
        t[ty + l * 8][tx] = wp[((size_t)h * DD + d) * DK + kk0 + tx];
    }
    __syncthreads();
    #pragma unroll
    for (int l = 0; l < 4; l++) {
        int n = np0 + ty + l * 8;
        wt[((size_t)p * DD + n) * DD + d0 + tx] = t[tx][ty + l * 8];
    }
}

__global__ void qkv_bias_pack_kernel(
    const float* __restrict__ bq, const float* __restrict__ bk,
    const float* __restrict__ bv, float* __restrict__ bt)
{
    int p = blockIdx.x, i = threadIdx.x;    // <<<3, 768>>>
    const float* bp = (p == 0) ? bq : (p == 1) ? bk : bv;
    bt[p * DD + i] = bp[i];
}

// ============ TF32 mma.sync GEMM: C[M,N] = A[M,K] @ Bt[N,K]^T =============
// Block 128x128, BK=32, 256 threads = 8 warps (2 m x 4 n), warp tile 64x32.
// smem (dynamic, 64KB): sA[2][4096] u32 fragment-layout, sB[2][4096].
//   A-frag layout: [matom8][kstep4][lane32][reg4]  -> LDS.128 reads
//   B-frag layout: [natom16][kstep4][lane32][reg2] -> LDS.64 reads
#define GEMM_SMEM (16384 * 4)

template<bool GELU, bool RES>
__global__ void __launch_bounds__(256) tc_gemm(
    const float* __restrict__ A, const float* __restrict__ Bt,
    const float* __restrict__ bias, const float* __restrict__ res,
    float* __restrict__ C, int N, int K)
{
    extern __shared__ uint32_t sh[];
    uint32_t* sA = sh;          // [2][4096]
    uint32_t* sB = sh + 8192;   // [2][4096]
    int tid = threadIdx.x, lane = tid & 31, wid = tid >> 5;
    int wm = wid & 1, wn = wid >> 1;      // 2 x 4 warp grid
    int bm = blockIdx.y, bn = blockIdx.x;

    const float* Ag = A  + (size_t)(bm * 128) * K;
    const float* Bg = Bt + (size_t)(bn * 128) * K;

    // per-thread staging geometry (4 float4 each for A and B per chunk)
    int aD[4], aS[4], bD[4];
    #pragma unroll
    for (int i = 0; i < 4; i++) {
        int idx = tid + i * 256;
        int r = idx >> 3, cg = idx & 7;
        int ma = r >> 4, row = r & 15, ks = cg >> 1, hf = cg & 1;
        aD[i] = ((ma * 4 + ks) * 32 + (row & 7) * 4) * 4 + (row >> 3) + 2 * hf;
        aS[i] = r * K + cg * 4;
        int na = r >> 3, nn = r & 7;
        bD[i] = ((na * 4 + ks) * 32 + nn * 4) * 2 + hf;
    }

    float acc[4][4][4];
    #pragma unroll
    for (int mi = 0; mi < 4; mi++)
        #pragma unroll
        for (int ni = 0; ni < 4; ni++)
            #pragma unroll
            for (int r = 0; r < 4; r++) acc[mi][ni][r] = 0.0f;

    // stage chunk 0 into buffer 0
    #pragma unroll
    for (int i = 0; i < 4; i++) {
        float4 v = *(const float4*)(Ag + aS[i]);
        sA[aD[i]+0]  = f2tf(v.x); sA[aD[i]+4]  = f2tf(v.y);
        sA[aD[i]+8]  = f2tf(v.z); sA[aD[i]+12] = f2tf(v.w);
        float4 w = *(const float4*)(Bg + aS[i]);
        sB[bD[i]+0] = f2tf(w.x); sB[bD[i]+2] = f2tf(w.y);
        sB[bD[i]+4] = f2tf(w.z); sB[bD[i]+6] = f2tf(w.w);
    }
    __syncthreads();

    int NT = K >> 5;
    for (int t = 0; t < NT; t++) {
        float4 pa[4], pb[4];
        bool pf = (t + 1 < NT);
        if (pf) {
            int k0 = (t + 1) * 32;
            #pragma unroll
            for (int i = 0; i < 4; i++) {
                pa[i] = *(const float4*)(Ag + aS[i] + k0);
                pb[i] = *(const float4*)(Bg + aS[i] + k0);
            }
        }
        const uint32_t* cA = sA + (t & 1) * 4096;
        const uint32_t* cB = sB + (t & 1) * 4096;
        #pragma unroll
        for (int ks = 0; ks < 4; ks++) {
            uint32_t ua[4][4], ub[4][2];
            #pragma unroll
            for (int mi = 0; mi < 4; mi++)
                *(uint4*)ua[mi] = *(const uint4*)&cA[(((wm*4+mi)*4 + ks)*32 + lane)*4];
            #pragma unroll
            for (int ni = 0; ni < 4; ni++)
                *(uint2*)ub[ni] = *(const uint2*)&cB[(((wn*4+ni)*4 + ks)*32 + lane)*2];
            #pragma unroll
            for (int mi = 0; mi < 4; mi++)
                #pragma unroll
                for (int ni = 0; ni < 4; ni++)
                    mma8(acc[mi][ni], ua[mi], ub[ni]);
        }
        if (pf) {
            uint32_t* nA = sA + ((t + 1) & 1) * 4096;
            uint32_t* nB = sB + ((t + 1) & 1) * 4096;
            #pragma unroll
            for (int i = 0; i < 4; i++) {
                nA[aD[i]+0]  = f2tf(pa[i].x); nA[aD[i]+4]  = f2tf(pa[i].y);
                nA[aD[i]+8]  = f2tf(pa[i].z); nA[aD[i]+12] = f2tf(pa[i].w);
                nB[bD[i]+0] = f2tf(pb[i].x); nB[bD[i]+2] = f2tf(pb[i].y);
                nB[bD[i]+4] = f2tf(pb[i].z); nB[bD[i]+6] = f2tf(pb[i].w);
            }
        }
        __syncthreads();
    }

    // epilogue: C-frag direct to global
    int g = lane >> 2, T = lane & 3;
    #pragma unroll
    for (int mi = 0; mi < 4; mi++) {
        int row0 = bm * 128 + wm * 64 + mi * 16 + g;
        #pragma unroll
        for (int ni = 0; ni < 4; ni++) {
            int col = bn * 128 + wn * 32 + ni * 8 + 2 * T;
            float b0 = bias[col], b1 = bias[col + 1];
            #pragma unroll
            for (int hh = 0; hh < 2; hh++) {
                int rr = row0 + hh * 8;
                float v0 = acc[mi][ni][2*hh]   + b0;
                float v1 = acc[mi][ni][2*hh+1] + b1;
                if (GELU) { v0 = gelu_f(v0); v1 = gelu_f(v1); }
                if (RES) {
                    float2 rv = *(const float2*)(res + (size_t)rr * N + col);
                    v0 += rv.x; v1 += rv.y;
                }
                *(float2*)(C + (size_t)rr * N + col) = make_float2(v0, v1);
            }
        }
    }
}

// ============ flash attention via mma.sync tf32 ===========================
// grid (S/128, B*H), 256 threads = 8 warps, each warp = 16 query rows.
// Key tiles of 64. smem 96KB: QF(32K) KF(16K) VF(16K) PF(32K), fragment layouts.
#define ATTN_SMEM (24576 * 4)

__global__ void __launch_bounds__(256) attn_kernel(
    const float* __restrict__ qkv, float* __restrict__ o)
{
    extern __shared__ uint32_t sh[];
    uint32_t* QF = sh;            // [warp8][kstep8][lane32][4]
    uint32_t* KF = sh + 8192;     // [natom8][kstep8][lane32][2]
    uint32_t* VF = sh + 12288;    // [natom8][kstep8][lane32][2]
    uint32_t* PF = sh + 16384;    // [warp8][kstep8][lane32][4]

    int tid = threadIdx.x, lane = tid & 31, wid = tid >> 5;
    int g = lane >> 2, T = lane & 3;
    int bh = blockIdx.y, b_ = bh / HH, h_ = bh % HH;
    int q0 = blockIdx.x * 128;
    size_t baseTok = (size_t)b_ * SS;

    // ---- stage Q (pre-scaled by 1/8), A-fragment layout ----
    #pragma unroll
    for (int i = 0; i < 8; i++) {
        int idx = tid + i * 256;
        int r = idx >> 4, cg = idx & 15;
        int wf = r >> 4, row = r & 15, ks = cg >> 1, hf = cg & 1;
        int d = ((wf * 8 + ks) * 32 + (row & 7) * 4) * 4 + (row >> 3) + 2 * hf;
        float4 v = *(const float4*)(qkv + (baseTok + q0 + r) * NQKV + h_ * 64 + cg * 4);
        QF[d+0]  = f2tf(v.x * 0.125f); QF[d+4]  = f2tf(v.y * 0.125f);
        QF[d+8]  = f2tf(v.z * 0.125f); QF[d+12] = f2tf(v.w * 0.125f);
    }

    // K/V staging geometry
    int kD[4], vD[4]; size_t kS[4], vS[4];
    #pragma unroll
    for (int i = 0; i < 4; i++) {
        int idx = tid + i * 256;
        int key = idx >> 4, cg = idx & 15;
        { int na = key >> 3, ks = cg >> 1, hf = cg & 1;
          kD[i] = ((na * 8 + ks) * 32 + (key & 7) * 4) * 2 + hf;
          kS[i] = (baseTok + key) * NQKV + DD + h_ * 64 + cg * 4; }
        { int na = cg >> 1, ks = key >> 3;
          int lb = (4 * (cg & 1)) * 4 + (key & 3);
          vD[i] = ((na * 8 + ks) * 32 + lb) * 2 + ((key >> 2) & 1);
          vS[i] = (baseTok + key) * NQKV + 2 * DD + h_ * 64 + cg * 4; }
    }

    float oacc[8][4];
    #pragma unroll
    for (int na = 0; na < 8; na++)
        #pragma unroll
        for (int r = 0; r < 4; r++) oacc[na][r] = 0.0f;
    float m0 = -1e30f, m1 = -1e30f, l0 = 0.0f, l1 = 0.0f;

    // PF write offsets (C-frag -> A-frag mapping)
    int lt0 = g * 4 + ((2 * T) & 3);
    int lt1 = g * 4 + ((2 * T + 1) & 3);
    int rb = (T >= 2) ? 2 : 0;
    uint32_t* pfw = PF + wid * 1024;

    for (int s0 = 0; s0 < SS; s0 += 64) {
        __syncthreads();
        #pragma unroll
        for (int i = 0; i < 4; i++) {
            float4 kv = *(const float4*)(qkv + kS[i] + (size_t)s0 * NQKV);
            KF[kD[i]+0] = f2tf(kv.x); KF[kD[i]+2] = f2tf(kv.y);
            KF[kD[i]+4] = f2tf(kv.z); KF[kD[i]+6] = f2tf(kv.w);
            float4 vv = *(const float4*)(qkv + vS[i] + (size_t)s0 * NQKV);
            VF[vD[i]+0]  = f2tf(vv.x); VF[vD[i]+8]  = f2tf(vv.y);
            VF[vD[i]+16] = f2tf(vv.z); VF[vD[i]+24] = f2tf(vv.w);
        }
        __syncthreads();

        // S = Q @ K^T
        float sacc[8][4];
        #pragma unroll
        for (int na = 0; na < 8; na++)
            #pragma unroll
            for (int r = 0; r < 4; r++) sacc[na][r] = 0.0f;
        #pragma unroll
        for (int ks = 0; ks < 8; ks++) {
            uint32_t qa[4];
            *(uint4*)qa = *(const uint4*)&QF[((wid * 8 + ks) * 32 + lane) * 4];
            #pragma unroll
            for (int na = 0; na < 8; na++) {
                uint32_t kb[2];
                *(uint2*)kb = *(const uint2*)&KF[((na * 8 + ks) * 32 + lane) * 2];
                mma8(sacc[na], qa, kb);
            }
        }

        // online softmax (rows g and g+8; reduce over quad lanes)
        float rm0 = -1e30f, rm1 = -1e30f;
        #pragma unroll
        for (int na = 0; na < 8; na++) {
            rm0 = fmaxf(rm0, fmaxf(sacc[na][0], sacc[na][1]));
            rm1 = fmaxf(rm1, fmaxf(sacc[na][2], sacc[na][3]));
        }
        rm0 = fmaxf(rm0, __shfl_xor_sync(0xffffffffu, rm0, 1));
        rm0 = fmaxf(rm0, __shfl_xor_sync(0xffffffffu, rm0, 2));
        rm1 = fmaxf(rm1, __shfl_xor_sync(0xffffffffu, rm1, 1));
        rm1 = fmaxf(rm1, __shfl_xor_sync(0xffffffffu, rm1, 2));
        float mn0 = fmaxf(m0, rm0), mn1 = fmaxf(m1, rm1);
        float al0 = __expf(m0 - mn0), al1 = __expf(m1 - mn1);
        m0 = mn0; m1 = mn1;
        float rs0 = 0.0f, rs1 = 0.0f;
        #pragma unroll
        for (int na = 0; na < 8; na++) {
            float e0 = __expf(sacc[na][0] - mn0);
            float e1 = __expf(sacc[na][1] - mn0);
            float e2 = __expf(sacc[na][2] - mn1);
            float e3 = __expf(sacc[na][3] - mn1);
            rs0 += e0 + e1; rs1 += e2 + e3;
            pfw[(na * 32 + lt0) * 4 + rb]     = f2tf(e0);
            pfw[(na * 32 + lt1) * 4 + rb]     = f2tf(e1);
            pfw[(na * 32 + lt0) * 4 + rb + 1] = f2tf(e2);
            pfw[(na * 32 + lt1) * 4 + rb + 1] = f2tf(e3);
        }
        rs0 += __shfl_xor_sync(0xffffffffu, rs0, 1);
        rs0 += __shfl_xor_sync(0xffffffffu, rs0, 2);
        rs1 += __shfl_xor_sync(0xffffffffu, rs1, 1);
        rs1 += __shfl_xor_sync(0xffffffffu, rs1, 2);
        l0 = l0 * al0 + rs0; l1 = l1 * al1 + rs1;
        #pragma unroll
        for (int na = 0; na < 8; na++) {
            oacc[na][0] *= al0; oacc[na][1] *= al0;
            oacc[na][2] *= al1; oacc[na][3] *= al1;
        }
        __syncwarp();

        // O += P @ V
        #pragma unroll
        for (int ks = 0; ks < 8; ks++) {
            uint32_t pa[4];
            *(uint4*)pa = *(const uint4*)&pfw[(ks * 32 + lane) * 4];
            #pragma unroll
            for (int na = 0; na < 8; na++) {
                uint32_t vb[2];
                *(uint2*)vb = *(const uint2*)&VF[((na * 8 + ks) * 32 + lane) * 2];
                mma8(oacc[na], pa, vb);
            }
        }
    }

    // epilogue
    float inv0 = 1.0f / l0, inv1 = 1.0f / l1;
    int row0 = q0 + wid * 16 + g;
    #pragma unroll
    for (int na = 0; na < 8; na++) {
        int col = h_ * 64 + na * 8 + 2 * T;
        *(float2*)(o + (baseTok + row0)     * DD + col) =
            make_float2(oacc[na][0] * inv0, oacc[na][1] * inv0);
        *(float2*)(o + (baseTok + row0 + 8) * DD + col) =
            make_float2(oacc[na][2] * inv1, oacc[na][3] * inv1);
    }
}

// ---------------- launch ---------------------------------------------------
extern "C" void kernel_launch(void* const* d_in, const int* in_sizes, int n_in,
                              void* d_out, int out_size)
{
    (void)in_sizes; (void)n_in; (void)out_size;
    const float* x    = (const float*)d_in[0];
    const float* wq_w = (const float*)d_in[1];
    const float* wq_b = (const float*)d_in[2];
    const float* wk_w = (const float*)d_in[3];
    const float* wk_b = (const float*)d_in[4];
    const float* wv_w = (const float*)d_in[5];
    const float* wv_b = (const float*)d_in[6];
    const float* wo_w = (const float*)d_in[7];
    const float* wo_b = (const float*)d_in[8];
    const float* ln_g = (const float*)d_in[9];
    const float* ln_b = (const float*)d_in[10];
    const float* w1   = (const float*)d_in[11];
    const float* b1   = (const float*)d_in[12];
    const float* w2   = (const float*)d_in[13];
    const float* b2   = (const float*)d_in[14];
    float* out = (float*)d_out;

    float *h, *qkv, *o, *y, *z, *u, *wtq, *btq, *wto, *wt1, *wt2;
    cudaGetSymbolAddress((void**)&h,   g_h);
    cudaGetSymbolAddress((void**)&qkv, g_qkv);
    cudaGetSymbolAddress((void**)&o,   g_o);
    cudaGetSymbolAddress((void**)&y,   g_y);
    cudaGetSymbolAddress((void**)&z,   g_z);
    cudaGetSymbolAddress((void**)&u,   g_u);
    cudaGetSymbolAddress((void**)&wtq, g_wtq);
    cudaGetSymbolAddress((void**)&btq, g_btq);
    cudaGetSymbolAddress((void**)&wto, g_wto);
    cudaGetSymbolAddress((void**)&wt1, g_wt1);
    cudaGetSymbolAddress((void**)&wt2, g_wt2);

    cudaFuncSetAttribute(tc_gemm<false, false>, cudaFuncAttributeMaxDynamicSharedMemorySize, GEMM_SMEM);
    cudaFuncSetAttribute(tc_gemm<false, true >, cudaFuncAttributeMaxDynamicSharedMemorySize, GEMM_SMEM);
    cudaFuncSetAttribute(tc_gemm<true,  false>, cudaFuncAttributeMaxDynamicSharedMemorySize, GEMM_SMEM);
    cudaFuncSetAttribute(attn_kernel, cudaFuncAttributeMaxDynamicSharedMemorySize, ATTN_SMEM);

    dim3 tb(32, 8);

    // 0) weight packing/transposes
    qkv_pack_kernel<<<dim3(DD/32, DD/32, 3), tb>>>(wq_w, wk_w, wv_w, wtq);
    qkv_bias_pack_kernel<<<3, DD>>>(wq_b, wk_b, wv_b, btq);
    transpose_kernel<<<dim3(DD/32, DD/32), tb>>>(wo_w, wto, DD, DD);
    transpose_kernel<<<dim3(FF/32, DD/32), tb>>>(w1, wt1, DD, FF);
    transpose_kernel<<<dim3(DD/32, FF/32), tb>>>(w2, wt2, FF, DD);

    // 1) LN1
    ln_kernel<<<MM, 256>>>(x, ln_g, ln_b, h);

    // 2) fused QKV projection: [4096, 2304]
    tc_gemm<false, false><<<dim3(NQKV/128, MM/128), 256, GEMM_SMEM>>>(h, wtq, btq, nullptr, qkv, NQKV, DD);

    // 3) attention
    attn_kernel<<<dim3(SS/128, BB*HH), 256, ATTN_SMEM>>>(qkv, o);

    // 4) O-proj + bias + residual(x)
    tc_gemm<false, true><<<dim3(DD/128, MM/128), 256, GEMM_SMEM>>>(o, wto, wo_b, x, y, DD, DD);

    // 5) LN2
    ln_kernel<<<MM, 256>>>(y, ln_g, ln_b, z);

    // 6) FFN1 + bias + exact GELU
    tc_gemm<true, false><<<dim3(FF/128, MM/128), 256, GEMM_SMEM>>>(z, wt1, b1, nullptr, u, FF, DD);

    // 7) FFN2 + bias + residual(y) -> out
    tc_gemm<false, true><<<dim3(DD/128, MM/128), 256, GEMM_SMEM>>>(u, wt2, b2, y, out, DD, FF);
}

// round 9
// speedup vs baseline: 2.9773x; 1.4244x over previous
#include <cuda_runtime.h>
#include <math.h>
#include <cstdint>

// ---------------- problem dims (fixed) ----------------
#define BB   2
#define SS   2048
#define DD   768
#define HH   12
#define DK   64
#define FF   3072
#define MM   (BB*SS)          // 4096 tokens
#define NQKV (3*DD)           // 2304 fused QKV cols

// ---------------- scratch (device globals; allocation-free) ----------------
__device__ float g_h[MM*DD];            // LN1 output (tf32-rounded)
__device__ float g_qkv[MM*NQKV];        // fused QKV [M, 2304] (tf32-rounded)
__device__ float g_vt[BB*HH*DK*SS];     // V transposed: [bh][d][s] (tf32)
__device__ float g_o[MM*DD];            // attn output (tf32-rounded)
__device__ float g_y[MM*DD];            // after O-proj + residual (fp32)
__device__ float g_z[MM*DD];            // LN2 output (tf32-rounded)
__device__ float g_u[MM*FF];            // FFN hidden (tf32-rounded)
__device__ float g_wtq[NQKV*DD];        // fused QKV weights^T (tf32)
__device__ float g_btq[NQKV];           // fused QKV bias
__device__ float g_wto[DD*DD];          // wo^T (tf32)
__device__ float g_wt1[FF*DD];          // w1^T (tf32)
__device__ float g_wt2[DD*FF];          // w2^T (tf32)

// ================= helpers =================
__device__ __forceinline__ uint32_t f2tf(float f) {
    uint32_t u; asm("cvt.rna.tf32.f32 %0, %1;" : "=r"(u) : "f"(f)); return u;
}
__device__ __forceinline__ float f2tff(float f) { return __uint_as_float(f2tf(f)); }
__device__ __forceinline__ void mma8(float* c, const uint32_t* a, const uint32_t* b) {
    asm volatile("mma.sync.aligned.m16n8k8.row.col.f32.tf32.tf32.f32 "
        "{%0,%1,%2,%3}, {%4,%5,%6,%7}, {%8,%9}, {%0,%1,%2,%3};"
        : "+f"(c[0]), "+f"(c[1]), "+f"(c[2]), "+f"(c[3])
        : "r"(a[0]), "r"(a[1]), "r"(a[2]), "r"(a[3]), "r"(b[0]), "r"(b[1]));
}
__device__ __forceinline__ float gelu_f(float v) {
    return 0.5f * v * (1.0f + erff(v * 0.70710678118654752f));
}

// ---------------- LayerNorm: one block per row, tf32-rounded output -------
__global__ void __launch_bounds__(256) ln_kernel(
    const float* __restrict__ x, const float* __restrict__ gw,
    const float* __restrict__ bw, float* __restrict__ out)
{
    int row = blockIdx.x;
    int tid = threadIdx.x;
    const float* xr = x + (size_t)row * DD;

    float v0 = xr[tid], v1 = xr[tid + 256], v2 = xr[tid + 512];
    float s = v0 + v1 + v2;

    __shared__ float red[8];
    #pragma unroll
    for (int o = 16; o > 0; o >>= 1) s += __shfl_xor_sync(0xffffffffu, s, o);
    if ((tid & 31) == 0) red[tid >> 5] = s;
    __syncthreads();
    float tot = red[0]+red[1]+red[2]+red[3]+red[4]+red[5]+red[6]+red[7];
    float mu = tot * (1.0f / 768.0f);

    float d0 = v0 - mu, d1 = v1 - mu, d2 = v2 - mu;
    float q = d0*d0 + d1*d1 + d2*d2;
    #pragma unroll
    for (int o = 16; o > 0; o >>= 1) q += __shfl_xor_sync(0xffffffffu, q, o);
    __syncthreads();
    if ((tid & 31) == 0) red[tid >> 5] = q;
    __syncthreads();
    float vtot = red[0]+red[1]+red[2]+red[3]+red[4]+red[5]+red[6]+red[7];
    float rstd = rsqrtf(vtot * (1.0f / 768.0f) + 1e-5f);

    float* orow = out + (size_t)row * DD;
    orow[tid]       = f2tff(d0 * rstd * gw[tid]       + bw[tid]);
    orow[tid + 256] = f2tff(d1 * rstd * gw[tid + 256] + bw[tid + 256]);
    orow[tid + 512] = f2tff(d2 * rstd * gw[tid + 512] + bw[tid + 512]);
}

// ---------------- unified weight prep (transposes + packs + bias) ---------
__device__ __forceinline__ void trans_tile(
    const float* __restrict__ W, float* __restrict__ Wt, int K, int N,
    int bx, int by, float t[32][33], int tx, int ty)
{
    #pragma unroll
    for (int l = 0; l < 4; l++) {
        int k = by * 32 + ty + l * 8;
        t[ty + l * 8][tx] = W[(size_t)k * N + bx * 32 + tx];
    }
    __syncthreads();
    #pragma unroll
    for (int l = 0; l < 4; l++) {
        int n = bx * 32 + ty + l * 8;
        Wt[(size_t)n * K + by * 32 + tx] = f2tff(t[tx][ty + l * 8]);
    }
}

// grid: 1728 (qkv) + 576 (wo) + 2304 (w1) + 2304 (w2) + 1 (bias) = 6913
__global__ void __launch_bounds__(256) prep_kernel(
    const float* __restrict__ wq, const float* __restrict__ wk,
    const float* __restrict__ wv, const float* __restrict__ bq,
    const float* __restrict__ bk, const float* __restrict__ bv,
    const float* __restrict__ wo, const float* __restrict__ w1,
    const float* __restrict__ w2,
    float* __restrict__ wtq, float* __restrict__ btq, float* __restrict__ wto,
    float* __restrict__ wt1, float* __restrict__ wt2)
{
    __shared__ float t[32][33];
    int id = blockIdx.x;
    int tx = threadIdx.x, ty = threadIdx.y;
    if (id < 1728) {
        int p = id / 576, rem = id % 576;
        int bx = rem % 24, by = rem / 24;
        const float* wp = (p == 0) ? wq : (p == 1) ? wk : wv;
        int np0 = bx * 32, d0 = by * 32;
        int h = np0 >> 6, kk0 = np0 & 63;
        #pragma unroll
        for (int l = 0; l < 4; l++) {
            int d = d0 + ty + l * 8;
            t[ty + l * 8][tx] = wp[((size_t)h * DD + d) * DK + kk0 + tx];
        }
        __syncthreads();
        #pragma unroll
        for (int l = 0; l < 4; l++) {
            int n = np0 + ty + l * 8;
            wtq[((size_t)p * DD + n) * DD + d0 + tx] = f2tff(t[tx][ty + l * 8]);
        }
    } else if (id < 2304) {
        int rem = id - 1728;
        trans_tile(wo, wto, DD, DD, rem % 24, rem / 24, t, tx, ty);
    } else if (id < 4608) {
        int rem = id - 2304;
        trans_tile(w1, wt1, DD, FF, rem % 96, rem / 96, t, tx, ty);
    } else if (id < 6912) {
        int rem = id - 4608;
        trans_tile(w2, wt2, FF, DD, rem % 24, rem / 24, t, tx, ty);
    } else {
        int tid = ty * 32 + tx;
        for (int i = tid; i < DD; i += 256) {
            btq[i] = bq[i]; btq[DD + i] = bk[i]; btq[2 * DD + i] = bv[i];
        }
    }
}

// ---------------- V transpose: qkv V-part -> vt[bh][d][s] -----------------
__global__ void __launch_bounds__(256) vtrans_kernel(
    const float* __restrict__ qkv, float* __restrict__ vt)
{
    __shared__ float t[32][33];
    int s0 = blockIdx.x * 32;
    int d0 = blockIdx.y * 32;
    int bh = blockIdx.z;
    int b_ = bh / HH, h_ = bh % HH;
    int tx = threadIdx.x, ty = threadIdx.y;
    #pragma unroll
    for (int l = 0; l < 4; l++) {
        int s = s0 + ty + l * 8;
        t[ty + l * 8][tx] = qkv[((size_t)(b_ * SS + s)) * NQKV + 2 * DD + h_ * 64 + d0 + tx];
    }
    __syncthreads();
    #pragma unroll
    for (int l = 0; l < 4; l++) {
        int d = d0 + ty + l * 8;
        vt[((size_t)bh * 64 + d) * SS + s0 + tx] = t[tx][ty + l * 8];
    }
}

// ============ TF32 mma.sync GEMM: C[M,N] = A[M,K] @ Bt[N,K]^T =============
// Block 128x128, BK=32, 256 threads = 8 warps (2m x 4n), warp tile 64x32.
// Fragment layouts with XOR-ks slot swizzle (conflict-light STS, CF LDS):
//   A slot = (ma*4+ks)*32 + (row&7)*4 + (q^ks); word = slot*4 + reg
//   B slot = (na*4+ks)*32 + (n&7)*4 + (q^ks);   word = slot*2 + hf
#define GEMM_SMEM (16384 * 4)

template<bool GELU, bool RES, bool TFOUT>
__global__ void __launch_bounds__(256, 2) tc_gemm(
    const float* __restrict__ A, const float* __restrict__ Bt,
    const float* __restrict__ bias, const float* __restrict__ res,
    float* __restrict__ C, int N, int K)
{
    extern __shared__ uint32_t sh[];
    uint32_t* sA = sh;          // [2][4096]
    uint32_t* sB = sh + 8192;   // [2][4096]
    int tid = threadIdx.x, lane = tid & 31, wid = tid >> 5;
    int wm = wid & 1, wn = wid >> 1;
    int bm = blockIdx.y, bn = blockIdx.x;

    const float* Ag = A  + (size_t)(bm * 128) * K;
    const float* Bg = Bt + (size_t)(bn * 128) * K;

    // staging geometry
    int ksw = (tid & 7) >> 1;
    int oa0 = ((0 ^ ksw) << 2), oa1 = ((1 ^ ksw) << 2),
        oa2 = ((2 ^ ksw) << 2), oa3 = ((3 ^ ksw) << 2);
    int ob0 = ((0 ^ ksw) << 1), ob1 = ((1 ^ ksw) << 1),
        ob2 = ((2 ^ ksw) << 1), ob3 = ((3 ^ ksw) << 1);
    int aD[4], aS[4], bD[4];
    #pragma unroll
    for (int i = 0; i < 4; i++) {
        int idx = tid + i * 256;
        int r = idx >> 3, cg = idx & 7;
        int ks = cg >> 1, hf = cg & 1;
        int ma = r >> 4, row = r & 15;
        aD[i] = ((ma * 4 + ks) * 32 + (row & 7) * 4) * 4 + (row >> 3) + 2 * hf;
        aS[i] = r * K + cg * 4;
        int na = r >> 3, nn = r & 7;
        bD[i] = ((na * 4 + ks) * 32 + nn * 4) * 2 + hf;
    }

    float acc[4][4][4];
    #pragma unroll
    for (int mi = 0; mi < 4; mi++)
        #pragma unroll
        for (int ni = 0; ni < 4; ni++)
            #pragma unroll
            for (int r = 0; r < 4; r++) acc[mi][ni][r] = 0.0f;

    // stage chunk 0 (inputs are pre-rounded tf32: pure bit copies)
    #pragma unroll
    for (int i = 0; i < 4; i++) {
        float4 v = *(const float4*)(Ag + aS[i]);
        sA[aD[i]+oa0] = __float_as_uint(v.x); sA[aD[i]+oa1] = __float_as_uint(v.y);
        sA[aD[i]+oa2] = __float_as_uint(v.z); sA[aD[i]+oa3] = __float_as_uint(v.w);
        float4 w = *(const float4*)(Bg + aS[i]);
        sB[bD[i]+ob0] = __float_as_uint(w.x); sB[bD[i]+ob1] = __float_as_uint(w.y);
        sB[bD[i]+ob2] = __float_as_uint(w.z); sB[bD[i]+ob3] = __float_as_uint(w.w);
    }
    __syncthreads();

    int NT = K >> 5;
    for (int t = 0; t < NT; t++) {
        float4 pa[4], pb[4];
        bool pf = (t + 1 < NT);
        if (pf) {
            int k0 = (t + 1) * 32;
            #pragma unroll
            for (int i = 0; i < 4; i++) {
                pa[i] = *(const float4*)(Ag + aS[i] + k0);
                pb[i] = *(const float4*)(Bg + aS[i] + k0);
            }
        }
        const uint32_t* cA = sA + (t & 1) * 4096;
        const uint32_t* cB = sB + (t & 1) * 4096;
        #pragma unroll
        for (int ks = 0; ks < 4; ks++) {
            int lx = lane ^ ks;
            uint32_t ua[4][4], ub[4][2];
            #pragma unroll
            for (int mi = 0; mi < 4; mi++)
                *(uint4*)ua[mi] = *(const uint4*)&cA[(((wm*4+mi)*4 + ks)*32 + lx)*4];
            #pragma unroll
            for (int ni = 0; ni < 4; ni++)
                *(uint2*)ub[ni] = *(const uint2*)&cB[(((wn*4+ni)*4 + ks)*32 + lx)*2];
            #pragma unroll
            for (int mi = 0; mi < 4; mi++)
                #pragma unroll
                for (int ni = 0; ni < 4; ni++)
                    mma8(acc[mi][ni], ua[mi], ub[ni]);
        }
        if (pf) {
            uint32_t* nA = sA + ((t + 1) & 1) * 4096;
            uint32_t* nB = sB + ((t + 1) & 1) * 4096;
            #pragma unroll
            for (int i = 0; i < 4; i++) {
                nA[aD[i]+oa0] = __float_as_uint(pa[i].x); nA[aD[i]+oa1] = __float_as_uint(pa[i].y);
                nA[aD[i]+oa2] = __float_as_uint(pa[i].z); nA[aD[i]+oa3] = __float_as_uint(pa[i].w);
                nB[bD[i]+ob0] = __float_as_uint(pb[i].x); nB[bD[i]+ob1] = __float_as_uint(pb[i].y);
                nB[bD[i]+ob2] = __float_as_uint(pb[i].z); nB[bD[i]+ob3] = __float_as_uint(pb[i].w);
            }
        }
        __syncthreads();
    }

    // epilogue: C-frag direct to global
    int g = lane >> 2, T = lane & 3;
    #pragma unroll
    for (int mi = 0; mi < 4; mi++) {
        int row0 = bm * 128 + wm * 64 + mi * 16 + g;
        #pragma unroll
        for (int ni = 0; ni < 4; ni++) {
            int col = bn * 128 + wn * 32 + ni * 8 + 2 * T;
            float b0 = bias[col], b1 = bias[col + 1];
            #pragma unroll
            for (int hh = 0; hh < 2; hh++) {
                int rr = row0 + hh * 8;
                float v0 = acc[mi][ni][2*hh]   + b0;
                float v1 = acc[mi][ni][2*hh+1] + b1;
                if (GELU) { v0 = gelu_f(v0); v1 = gelu_f(v1); }
                if (RES) {
                    float2 rv = *(const float2*)(res + (size_t)rr * N + col);
                    v0 += rv.x; v1 += rv.y;
                }
                if (TFOUT) { v0 = f2tff(v0); v1 = f2tff(v1); }
                *(float2*)(C + (size_t)rr * N + col) = make_float2(v0, v1);
            }
        }
    }
}

// ============ flash attention via mma.sync tf32 ===========================
// grid (S/128, B*H), 256 threads = 8 warps, each warp = 16 query rows.
// K from qkv, V from vt[bh][d][s]. Swizzled fragment layouts as GEMM.
#define ATTN_SMEM (24576 * 4)

__global__ void __launch_bounds__(256, 2) attn_kernel(
    const float* __restrict__ qkv, const float* __restrict__ vt,
    float* __restrict__ o)
{
    extern __shared__ uint32_t sh[];
    uint32_t* QF = sh;            // [warp8][ks8][lane32][4]
    uint32_t* KF = sh + 8192;     // [na8][ks8][lane32][2]
    uint32_t* VF = sh + 12288;    // [na8][ks8][lane32][2]
    uint32_t* PF = sh + 16384;    // [warp8][ks8][lane32][4]

    int tid = threadIdx.x, lane = tid & 31, wid = tid >> 5;
    int g = lane >> 2, T = lane & 3;
    int bh = blockIdx.y, b_ = bh / HH, h_ = bh % HH;
    int q0 = blockIdx.x * 128;
    size_t baseTok = (size_t)b_ * SS;

    int cg = tid & 15, ksq = cg >> 1, hfq = cg & 1;
    int sw = ksq & 3;
    int p0 = ((0 ^ sw) << 1), p1 = ((1 ^ sw) << 1),
        p2 = ((2 ^ sw) << 1), p3 = ((3 ^ sw) << 1);

    // ---- stage Q (pre-scaled by 1/8; qkv already tf32) ----
    #pragma unroll
    for (int i = 0; i < 8; i++) {
        int r = (tid >> 4) + i * 16;
        int wf = r >> 4, row = r & 15;
        int d = ((wf * 8 + ksq) * 32 + (row & 7) * 4) * 4 + (row >> 3) + 2 * hfq;
        float4 v = *(const float4*)(qkv + (baseTok + q0 + r) * NQKV + h_ * 64 + cg * 4);
        QF[d + (p0<<1)] = __float_as_uint(v.x * 0.125f);
        QF[d + (p1<<1)] = __float_as_uint(v.y * 0.125f);
        QF[d + (p2<<1)] = __float_as_uint(v.z * 0.125f);
        QF[d + (p3<<1)] = __float_as_uint(v.w * 0.125f);
    }

    // K/V staging geometry
    int kD[4], vD[4]; size_t kS[4], vS[4];
    #pragma unroll
    for (int i = 0; i < 4; i++) {
        int key = (tid >> 4) + i * 16;     // s-row for K, d-row for V
        kD[i] = (((key >> 3) * 8 + ksq) * 32 + (key & 7) * 4) * 2 + hfq;
        vD[i] = kD[i];
        kS[i] = (baseTok + key) * NQKV + DD + h_ * 64 + cg * 4;
        vS[i] = ((size_t)bh * 64 + key) * SS + cg * 4;
    }

    float oacc[8][4];
    #pragma unroll
    for (int na = 0; na < 8; na++)
        #pragma unroll
        for (int r = 0; r < 4; r++) oacc[na][r] = 0.0f;
    float m0 = -1e30f, m1 = -1e30f, l0 = 0.0f, l1 = 0.0f;

    // PF write offsets (C-frag -> A-frag, swizzled)
    int swp = (g >> 1) & 3;
    int plt0 = (g * 4 + ((2 * T) & 3)) ^ swp;
    int plt1 = (g * 4 + ((2 * T + 1) & 3)) ^ swp;
    int rb = (T >= 2) ? 2 : 0;
    uint32_t* pfw = PF + wid * 1024;
    int lxp = lane ^ ((lane >> 3) & 3);

    // prefetch first K/V tile
    float4 kreg[4], vreg[4];
    #pragma unroll
    for (int i = 0; i < 4; i++) {
        kreg[i] = *(const float4*)(qkv + kS[i]);
        vreg[i] = *(const float4*)(vt + vS[i]);
    }

    for (int s0 = 0; s0 < SS; s0 += 64) {
        __syncthreads();   // prev-iter VF/KF readers done
        #pragma unroll
        for (int i = 0; i < 4; i++) {
            KF[kD[i]+p0] = __float_as_uint(kreg[i].x);
            KF[kD[i]+p1] = __float_as_uint(kreg[i].y);
            KF[kD[i]+p2] = __float_as_uint(kreg[i].z);
            KF[kD[i]+p3] = __float_as_uint(kreg[i].w);
            VF[vD[i]+p0] = __float_as_uint(vreg[i].x);
            VF[vD[i]+p1] = __float_as_uint(vreg[i].y);
            VF[vD[i]+p2] = __float_as_uint(vreg[i].z);
            VF[vD[i]+p3] = __float_as_uint(vreg[i].w);
        }
        __syncthreads();
        if (s0 + 64 < SS) {
            #pragma unroll
            for (int i = 0; i < 4; i++) {
                kreg[i] = *(const float4*)(qkv + kS[i] + (size_t)(s0 + 64) * NQKV);
                vreg[i] = *(const float4*)(vt + vS[i] + s0 + 64);
            }
        }

        // S = Q @ K^T
        float sacc[8][4];
        #pragma unroll
        for (int na = 0; na < 8; na++)
            #pragma unroll
            for (int r = 0; r < 4; r++) sacc[na][r] = 0.0f;
        #pragma unroll
        for (int ks = 0; ks < 8; ks++) {
            int lx = lane ^ (ks & 3);
            uint32_t qa[4];
            *(uint4*)qa = *(const uint4*)&QF[((wid * 8 + ks) * 32 + lx) * 4];
            #pragma unroll
            for (int na = 0; na < 8; na++) {
                uint32_t kb[2];
                *(uint2*)kb = *(const uint2*)&KF[((na * 8 + ks) * 32 + lx) * 2];
                mma8(sacc[na], qa, kb);
            }
        }

        // online softmax (rows g and g+8; reduce over quad lanes)
        float rm0 = -1e30f, rm1 = -1e30f;
        #pragma unroll
        for (int na = 0; na < 8; na++) {
            rm0 = fmaxf(rm0, fmaxf(sacc[na][0], sacc[na][1]));
            rm1 = fmaxf(rm1, fmaxf(sacc[na][2], sacc[na][3]));
        }
        rm0 = fmaxf(rm0, __shfl_xor_sync(0xffffffffu, rm0, 1));
        rm0 = fmaxf(rm0, __shfl_xor_sync(0xffffffffu, rm0, 2));
        rm1 = fmaxf(rm1, __shfl_xor_sync(0xffffffffu, rm1, 1));
        rm1 = fmaxf(rm1, __shfl_xor_sync(0xffffffffu, rm1, 2));
        float mn0 = fmaxf(m0, rm0), mn1 = fmaxf(m1, rm1);
        float al0 = __expf(m0 - mn0), al1 = __expf(m1 - mn1);
        m0 = mn0; m1 = mn1;
        float rs0 = 0.0f, rs1 = 0.0f;
        #pragma unroll
        for (int na = 0; na < 8; na++) {
            float e0 = __expf(sacc[na][0] - mn0);
            float e1 = __expf(sacc[na][1] - mn0);
            float e2 = __expf(sacc[na][2] - mn1);
            float e3 = __expf(sacc[na][3] - mn1);
            rs0 += e0 + e1; rs1 += e2 + e3;
            pfw[(na * 32 + plt0) * 4 + rb]     = f2tf(e0);
            pfw[(na * 32 + plt1) * 4 + rb]     = f2tf(e1);
            pfw[(na * 32 + plt0) * 4 + rb + 1] = f2tf(e2);
            pfw[(na * 32 + plt1) * 4 + rb + 1] = f2tf(e3);
        }
        rs0 += __shfl_xor_sync(0xffffffffu, rs0, 1);
        rs0 += __shfl_xor_sync(0xffffffffu, rs0, 2);
        rs1 += __shfl_xor_sync(0xffffffffu, rs1, 1);
        rs1 += __shfl_xor_sync(0xffffffffu, rs1, 2);
        l0 = l0 * al0 + rs0; l1 = l1 * al1 + rs1;
        #pragma unroll
        for (int na = 0; na < 8; na++) {
            oacc[na][0] *= al0; oacc[na][1] *= al0;
            oacc[na][2] *= al1; oacc[na][3] *= al1;
        }
        __syncwarp();

        // O += P @ V
        #pragma unroll
        for (int ks = 0; ks < 8; ks++) {
            int lx = lane ^ (ks & 3);
            uint32_t pa[4];
            *(uint4*)pa = *(const uint4*)&pfw[(ks * 32 + lxp) * 4];
            #pragma unroll
            for (int na = 0; na < 8; na++) {
                uint32_t vb[2];
                *(uint2*)vb = *(const uint2*)&VF[((na * 8 + ks) * 32 + lx) * 2];
                mma8(oacc[na], pa, vb);
            }
        }
    }

    // epilogue (tf32-rounded: feeds O-proj GEMM)
    float inv0 = 1.0f / l0, inv1 = 1.0f / l1;
    int row0 = q0 + wid * 16 + g;
    #pragma unroll
    for (int na = 0; na < 8; na++) {
        int col = h_ * 64 + na * 8 + 2 * T;
        *(float2*)(o + (baseTok + row0)     * DD + col) =
            make_float2(f2tff(oacc[na][0] * inv0), f2tff(oacc[na][1] * inv0));
        *(float2*)(o + (baseTok + row0 + 8) * DD + col) =
            make_float2(f2tff(oacc[na][2] * inv1), f2tff(oacc[na][3] * inv1));
    }
}

// ---------------- launch ---------------------------------------------------
extern "C" void kernel_launch(void* const* d_in, const int* in_sizes, int n_in,
                              void* d_out, int out_size)
{
    (void)in_sizes; (void)n_in; (void)out_size;
    const float* x    = (const float*)d_in[0];
    const float* wq_w = (const float*)d_in[1];
    const float* wq_b = (const float*)d_in[2];
    const float* wk_w = (const float*)d_in[3];
    const float* wk_b = (const float*)d_in[4];
    const float* wv_w = (const float*)d_in[5];
    const float* wv_b = (const float*)d_in[6];
    const float* wo_w = (const float*)d_in[7];
    const float* wo_b = (const float*)d_in[8];
    const float* ln_g = (const float*)d_in[9];
    const float* ln_b = (const float*)d_in[10];
    const float* w1   = (const float*)d_in[11];
    const float* b1   = (const float*)d_in[12];
    const float* w2   = (const float*)d_in[13];
    const float* b2   = (const float*)d_in[14];
    float* out = (float*)d_out;

    float *h, *qkv, *vt, *o, *y, *z, *u, *wtq, *btq, *wto, *wt1, *wt2;
    cudaGetSymbolAddress((void**)&h,   g_h);
    cudaGetSymbolAddress((void**)&qkv, g_qkv);
    cudaGetSymbolAddress((void**)&vt,  g_vt);
    cudaGetSymbolAddress((void**)&o,   g_o);
    cudaGetSymbolAddress((void**)&y,   g_y);
    cudaGetSymbolAddress((void**)&z,   g_z);
    cudaGetSymbolAddress((void**)&u,   g_u);
    cudaGetSymbolAddress((void**)&wtq, g_wtq);
    cudaGetSymbolAddress((void**)&btq, g_btq);
    cudaGetSymbolAddress((void**)&wto, g_wto);
    cudaGetSymbolAddress((void**)&wt1, g_wt1);
    cudaGetSymbolAddress((void**)&wt2, g_wt2);

    cudaFuncSetAttribute(tc_gemm<false, false, true >, cudaFuncAttributeMaxDynamicSharedMemorySize, GEMM_SMEM);
    cudaFuncSetAttribute(tc_gemm<false, true,  false>, cudaFuncAttributeMaxDynamicSharedMemorySize, GEMM_SMEM);
    cudaFuncSetAttribute(tc_gemm<true,  false, true >, cudaFuncAttributeMaxDynamicSharedMemorySize, GEMM_SMEM);
    cudaFuncSetAttribute(attn_kernel, cudaFuncAttributeMaxDynamicSharedMemorySize, ATTN_SMEM);

    // 0) unified weight prep
    prep_kernel<<<6913, dim3(32, 8)>>>(wq_w, wk_w, wv_w, wq_b, wk_b, wv_b,
                                       wo_w, w1, w2, wtq, btq, wto, wt1, wt2);

    // 1) LN1 (tf32 out)
    ln_kernel<<<MM, 256>>>(x, ln_g, ln_b, h);

    // 2) fused QKV projection: [4096, 2304] (tf32 out)
    tc_gemm<false, false, true><<<dim3(NQKV/128, MM/128), 256, GEMM_SMEM>>>(h, wtq, btq, nullptr, qkv, NQKV, DD);

    // 2b) V transpose for attention PV operand
    vtrans_kernel<<<dim3(SS/32, 2, BB*HH), dim3(32, 8)>>>(qkv, vt);

    // 3) attention (tf32 out)
    attn_kernel<<<dim3(SS/128, BB*HH), 256, ATTN_SMEM>>>(qkv, vt, o);

    // 4) O-proj + bias + residual(x) -> fp32 y
    tc_gemm<false, true, false><<<dim3(DD/128, MM/128), 256, GEMM_SMEM>>>(o, wto, wo_b, x, y, DD, DD);

    // 5) LN2 (tf32 out)
    ln_kernel<<<MM, 256>>>(y, ln_g, ln_b, z);

    // 6) FFN1 + bias + exact GELU (tf32 out)
    tc_gemm<true, false, true><<<dim3(FF/128, MM/128), 256, GEMM_SMEM>>>(z, wt1, b1, nullptr, u, FF, DD);

    // 7) FFN2 + bias + residual(y) -> out (fp32)
    tc_gemm<false, true, false><<<dim3(DD/128, MM/128), 256, GEMM_SMEM>>>(u, wt2, b2, y, out, DD, FF);
}

// round 11
// speedup vs baseline: 3.3775x; 1.1344x over previous
#include <cuda_runtime.h>
#include <cuda_bf16.h>
#include <math.h>
#include <cstdint>

// ---------------- problem dims (fixed) ----------------
#define BB   2
#define SS   2048
#define DD   768
#define HH   12
#define DK   64
#define FF   3072
#define MM   (BB*SS)          // 4096 tokens
#define NQKV (3*DD)           // 2304 fused QKV cols

// ---------------- scratch (device globals; allocation-free) ----------------
__device__ float g_h[MM*DD];            // LN1 output (tf32-rounded)
__device__ float g_qkv[MM*NQKV];        // fused QKV [M, 2304] (tf32-rounded)
__device__ __nv_bfloat16 g_vt16[BB*HH*DK*SS]; // V transposed [bh][d][s], bf16 pairs
__device__ float g_o[MM*DD];            // attn output (tf32-rounded)
__device__ float g_y[MM*DD];            // after O-proj + residual (fp32)
__device__ float g_z[MM*DD];            // LN2 output (tf32-rounded)
__device__ float g_u[MM*FF];            // FFN hidden (tf32-rounded)
__device__ float g_wtq[NQKV*DD];        // fused QKV weights^T (tf32)
__device__ float g_btq[NQKV];           // fused QKV bias
__device__ float g_wto[DD*DD];          // wo^T (tf32)
__device__ float g_wt1[FF*DD];          // w1^T (tf32)
__device__ float g_wt2[DD*FF];          // w2^T (tf32)

// ================= helpers =================
__device__ __forceinline__ uint32_t f2tf(float f) {
    uint32_t u; asm("cvt.rna.tf32.f32 %0, %1;" : "=r"(u) : "f"(f)); return u;
}
__device__ __forceinline__ float f2tff(float f) { return __uint_as_float(f2tf(f)); }
__device__ __forceinline__ void mma8(float* c, const uint32_t* a, const uint32_t* b) {
    asm volatile("mma.sync.aligned.m16n8k8.row.col.f32.tf32.tf32.f32 "
        "{%0,%1,%2,%3}, {%4,%5,%6,%7}, {%8,%9}, {%0,%1,%2,%3};"
        : "+f"(c[0]), "+f"(c[1]), "+f"(c[2]), "+f"(c[3])
        : "r"(a[0]), "r"(a[1]), "r"(a[2]), "r"(a[3]), "r"(b[0]), "r"(b[1]));
}
__device__ __forceinline__ void mma16bf(float* c, const uint32_t* a, const uint32_t* b) {
    asm volatile("mma.sync.aligned.m16n8k16.row.col.f32.bf16.bf16.f32 "
        "{%0,%1,%2,%3}, {%4,%5,%6,%7}, {%8,%9}, {%0,%1,%2,%3};"
        : "+f"(c[0]), "+f"(c[1]), "+f"(c[2]), "+f"(c[3])
        : "r"(a[0]), "r"(a[1]), "r"(a[2]), "r"(a[3]), "r"(b[0]), "r"(b[1]));
}
// pack: lo -> bits[15:0], hi -> bits[31:16]
__device__ __forceinline__ uint32_t packbf(float lo, float hi) {
    uint32_t d;
    asm("cvt.rn.bf16x2.f32 %0, %1, %2;" : "=r"(d) : "f"(hi), "f"(lo));
    return d;
}
__device__ __forceinline__ float gelu_f(float v) {
    return 0.5f * v * (1.0f + erff(v * 0.70710678118654752f));
}

// ---------------- LN body (callable from prep and ln2 kernels) ------------
__device__ __forceinline__ void ln_body(
    const float* __restrict__ x, const float* __restrict__ gw,
    const float* __restrict__ bw, float* __restrict__ out,
    int row, int tid, float* red)
{
    const float* xr = x + (size_t)row * DD;
    float v0 = xr[tid], v1 = xr[tid + 256], v2 = xr[tid + 512];
    float s = v0 + v1 + v2;
    #pragma unroll
    for (int o = 16; o > 0; o >>= 1) s += __shfl_xor_sync(0xffffffffu, s, o);
    if ((tid & 31) == 0) red[tid >> 5] = s;
    __syncthreads();
    float tot = red[0]+red[1]+red[2]+red[3]+red[4]+red[5]+red[6]+red[7];
    float mu = tot * (1.0f / 768.0f);
    float d0 = v0 - mu, d1 = v1 - mu, d2 = v2 - mu;
    float q = d0*d0 + d1*d1 + d2*d2;
    #pragma unroll
    for (int o = 16; o > 0; o >>= 1) q += __shfl_xor_sync(0xffffffffu, q, o);
    __syncthreads();
    if ((tid & 31) == 0) red[tid >> 5] = q;
    __syncthreads();
    float vtot = red[0]+red[1]+red[2]+red[3]+red[4]+red[5]+red[6]+red[7];
    float rstd = rsqrtf(vtot * (1.0f / 768.0f) + 1e-5f);
    float* orow = out + (size_t)row * DD;
    orow[tid]       = f2tff(d0 * rstd * gw[tid]       + bw[tid]);
    orow[tid + 256] = f2tff(d1 * rstd * gw[tid + 256] + bw[tid + 256]);
    orow[tid + 512] = f2tff(d2 * rstd * gw[tid + 512] + bw[tid + 512]);
}

__global__ void __launch_bounds__(256) ln_kernel(
    const float* __restrict__ x, const float* __restrict__ gw,
    const float* __restrict__ bw, float* __restrict__ out)
{
    __shared__ float red[8];
    ln_body(x, gw, bw, out, blockIdx.x, threadIdx.x, red);
}

// ---------------- unified prep: weight transposes + packs + bias + LN1 ----
__device__ __forceinline__ void trans_tile(
    const float* __restrict__ W, float* __restrict__ Wt, int K, int N,
    int bx, int by, float t[32][33], int tx, int ty)
{
    #pragma unroll
    for (int l = 0; l < 4; l++) {
        int k = by * 32 + ty + l * 8;
        t[ty + l * 8][tx] = W[(size_t)k * N + bx * 32 + tx];
    }
    __syncthreads();
    #pragma unroll
    for (int l = 0; l < 4; l++) {
        int n = bx * 32 + ty + l * 8;
        Wt[(size_t)n * K + by * 32 + tx] = f2tff(t[tx][ty + l * 8]);
    }
}

// grid: 1728 (qkv) + 576 (wo) + 2304 (w1) + 2304 (w2) + 1 (bias) + 4096 (ln1)
__global__ void __launch_bounds__(256) prep_kernel(
    const float* __restrict__ wq, const float* __restrict__ wk,
    const float* __restrict__ wv, const float* __restrict__ bq,
    const float* __restrict__ bk, const float* __restrict__ bv,
    const float* __restrict__ wo, const float* __restrict__ w1,
    const float* __restrict__ w2, const float* __restrict__ x,
    const float* __restrict__ ln_g, const float* __restrict__ ln_b,
    float* __restrict__ wtq, float* __restrict__ btq, float* __restrict__ wto,
    float* __restrict__ wt1, float* __restrict__ wt2, float* __restrict__ h)
{
    __shared__ float t[32][33];
    __shared__ float red[8];
    int id = blockIdx.x;
    int tx = threadIdx.x, ty = threadIdx.y;
    int tid = ty * 32 + tx;
    if (id < 1728) {
        int p = id / 576, rem = id % 576;
        int bx = rem % 24, by = rem / 24;
        const float* wp = (p == 0) ? wq : (p == 1) ? wk : wv;
        int np0 = bx * 32, d0 = by * 32;
        int hh = np0 >> 6, kk0 = np0 & 63;
        #pragma unroll
        for (int l = 0; l < 4; l++) {
            int d = d0 + ty + l * 8;
            t[ty + l * 8][tx] = wp[((size_t)hh * DD + d) * DK + kk0 + tx];
        }
        __syncthreads();
        #pragma unroll
        for (int l = 0; l < 4; l++) {
            int n = np0 + ty + l * 8;
            wtq[((size_t)p * DD + n) * DD + d0 + tx] = f2tff(t[tx][ty + l * 8]);
        }
    } else if (id < 2304) {
        int rem = id - 1728;
        trans_tile(wo, wto, DD, DD, rem % 24, rem / 24, t, tx, ty);
    } else if (id < 4608) {
        int rem = id - 2304;
        trans_tile(w1, wt1, DD, FF, rem % 96, rem / 96, t, tx, ty);
    } else if (id < 6912) {
        int rem = id - 4608;
        trans_tile(w2, wt2, FF, DD, rem % 24, rem / 24, t, tx, ty);
    } else if (id == 6912) {
        for (int i = tid; i < DD; i += 256) {
            btq[i] = bq[i]; btq[DD + i] = bk[i]; btq[2 * DD + i] = bv[i];
        }
    } else {
        ln_body(x, ln_g, ln_b, h, id - 6913, tid, red);
    }
}

// ---------------- V transpose: qkv V-part -> vt16[bh][d][s] bf16 ----------
__global__ void __launch_bounds__(256) vtrans_kernel(
    const float* __restrict__ qkv, __nv_bfloat16* __restrict__ vt16)
{
    __shared__ float t[32][33];
    int s0 = blockIdx.x * 32;
    int d0 = blockIdx.y * 32;
    int bh = blockIdx.z;
    int b_ = bh / HH, h_ = bh % HH;
    int tx = threadIdx.x, ty = threadIdx.y;
    #pragma unroll
    for (int l = 0; l < 4; l++) {
        int s = s0 + ty + l * 8;
        t[ty + l * 8][tx] = qkv[((size_t)(b_ * SS + s)) * NQKV + 2 * DD + h_ * 64 + d0 + tx];
    }
    __syncthreads();
    if (tx < 16) {
        #pragma unroll
        for (int l = 0; l < 4; l++) {
            int d = d0 + ty + l * 8;
            uint32_t w = packbf(t[2 * tx][ty + l * 8], t[2 * tx + 1][ty + l * 8]);
            uint32_t* orow = (uint32_t*)(vt16 + ((size_t)bh * 64 + d) * SS + s0);
            orow[tx] = w;
        }
    }
}

// ============ TF32 mma.sync GEMM (unchanged from R9) ======================
#define GEMM_SMEM (16384 * 4)

template<bool GELU, bool RES, bool TFOUT>
__global__ void __launch_bounds__(256, 2) tc_gemm(
    const float* __restrict__ A, const float* __restrict__ Bt,
    const float* __restrict__ bias, const float* __restrict__ res,
    float* __restrict__ C, int N, int K)
{
    extern __shared__ uint32_t sh[];
    uint32_t* sA = sh;          // [2][4096]
    uint32_t* sB = sh + 8192;   // [2][4096]
    int tid = threadIdx.x, lane = tid & 31, wid = tid >> 5;
    int wm = wid & 1, wn = wid >> 1;
    int bm = blockIdx.y, bn = blockIdx.x;

    const float* Ag = A  + (size_t)(bm * 128) * K;
    const float* Bg = Bt + (size_t)(bn * 128) * K;

    int ksw = (tid & 7) >> 1;
    int oa0 = ((0 ^ ksw) << 2), oa1 = ((1 ^ ksw) << 2),
        oa2 = ((2 ^ ksw) << 2), oa3 = ((3 ^ ksw) << 2);
    int ob0 = ((0 ^ ksw) << 1), ob1 = ((1 ^ ksw) << 1),
        ob2 = ((2 ^ ksw) << 1), ob3 = ((3 ^ ksw) << 1);
    int aD[4], aS[4], bD[4];
    #pragma unroll
    for (int i = 0; i < 4; i++) {
        int idx = tid + i * 256;
        int r = idx >> 3, cg = idx & 7;
        int ks = cg >> 1, hf = cg & 1;
        int ma = r >> 4, row = r & 15;
        aD[i] = ((ma * 4 + ks) * 32 + (row & 7) * 4) * 4 + (row >> 3) + 2 * hf;
        aS[i] = r * K + cg * 4;
        int na = r >> 3, nn = r & 7;
        bD[i] = ((na * 4 + ks) * 32 + nn * 4) * 2 + hf;
    }

    float acc[4][4][4];
    #pragma unroll
    for (int mi = 0; mi < 4; mi++)
        #pragma unroll
        for (int ni = 0; ni < 4; ni++)
            #pragma unroll
            for (int r = 0; r < 4; r++) acc[mi][ni][r] = 0.0f;

    #pragma unroll
    for (int i = 0; i < 4; i++) {
        float4 v = *(const float4*)(Ag + aS[i]);
        sA[aD[i]+oa0] = __float_as_uint(v.x); sA[aD[i]+oa1] = __float_as_uint(v.y);
        sA[aD[i]+oa2] = __float_as_uint(v.z); sA[aD[i]+oa3] = __float_as_uint(v.w);
        float4 w = *(const float4*)(Bg + aS[i]);
        sB[bD[i]+ob0] = __float_as_uint(w.x); sB[bD[i]+ob1] = __float_as_uint(w.y);
        sB[bD[i]+ob2] = __float_as_uint(w.z); sB[bD[i]+ob3] = __float_as_uint(w.w);
    }
    __syncthreads();

    int NT = K >> 5;
    for (int t = 0; t < NT; t++) {
        float4 pa[4], pb[4];
        bool pf = (t + 1 < NT);
        if (pf) {
            int k0 = (t + 1) * 32;
            #pragma unroll
            for (int i = 0; i < 4; i++) {
                pa[i] = *(const float4*)(Ag + aS[i] + k0);
                pb[i] = *(const float4*)(Bg + aS[i] + k0);
            }
        }
        const uint32_t* cA = sA + (t & 1) * 4096;
        const uint32_t* cB = sB + (t & 1) * 4096;
        #pragma unroll
        for (int ks = 0; ks < 4; ks++) {
            int lx = lane ^ ks;
            uint32_t ua[4][4], ub[4][2];
            #pragma unroll
            for (int mi = 0; mi < 4; mi++)
                *(uint4*)ua[mi] = *(const uint4*)&cA[(((wm*4+mi)*4 + ks)*32 + lx)*4];
            #pragma unroll
            for (int ni = 0; ni < 4; ni++)
                *(uint2*)ub[ni] = *(const uint2*)&cB[(((wn*4+ni)*4 + ks)*32 + lx)*2];
            #pragma unroll
            for (int mi = 0; mi < 4; mi++)
                #pragma unroll
                for (int ni = 0; ni < 4; ni++)
                    mma8(acc[mi][ni], ua[mi], ub[ni]);
        }
        if (pf) {
            uint32_t* nA = sA + ((t + 1) & 1) * 4096;
            uint32_t* nB = sB + ((t + 1) & 1) * 4096;
            #pragma unroll
            for (int i = 0; i < 4; i++) {
                nA[aD[i]+oa0] = __float_as_uint(pa[i].x); nA[aD[i]+oa1] = __float_as_uint(pa[i].y);
                nA[aD[i]+oa2] = __float_as_uint(pa[i].z); nA[aD[i]+oa3] = __float_as_uint(pa[i].w);
                nB[bD[i]+ob0] = __float_as_uint(pb[i].x); nB[bD[i]+ob1] = __float_as_uint(pb[i].y);
                nB[bD[i]+ob2] = __float_as_uint(pb[i].z); nB[bD[i]+ob3] = __float_as_uint(pb[i].w);
            }
        }
        __syncthreads();
    }

    int g = lane >> 2, T = lane & 3;
    #pragma unroll
    for (int mi = 0; mi < 4; mi++) {
        int row0 = bm * 128 + wm * 64 + mi * 16 + g;
        #pragma unroll
        for (int ni = 0; ni < 4; ni++) {
            int col = bn * 128 + wn * 32 + ni * 8 + 2 * T;
            float b0 = bias[col], b1 = bias[col + 1];
            #pragma unroll
            for (int hh = 0; hh < 2; hh++) {
                int rr = row0 + hh * 8;
                float v0 = acc[mi][ni][2*hh]   + b0;
                float v1 = acc[mi][ni][2*hh+1] + b1;
                if (GELU) { v0 = gelu_f(v0); v1 = gelu_f(v1); }
                if (RES) {
                    float2 rv = *(const float2*)(res + (size_t)rr * N + col);
                    v0 += rv.x; v1 += rv.y;
                }
                if (TFOUT) { v0 = f2tff(v0); v1 = f2tff(v1); }
                *(float2*)(C + (size_t)rr * N + col) = make_float2(v0, v1);
            }
        }
    }
}

// ============ flash attention: S in tf32 mma, PV in bf16 mma ==============
// grid (S/128, B*H), 256 threads = 8 warps, each warp = 16 query rows.
// smem 56KB: QF 32K (tf32 A-frag), KF 16K (tf32 B-frag), VF 8K (bf16 B-frag).
// P stays in registers: S C-frag -> bf16x2 pack == m16n8k16 A-frag.
#define ATTN_SMEM ((8192 + 4096 + 2048) * 4)

__global__ void __launch_bounds__(256, 2) attn_kernel(
    const float* __restrict__ qkv, const __nv_bfloat16* __restrict__ vt16,
    float* __restrict__ o)
{
    extern __shared__ uint32_t sh[];
    uint32_t* QF = sh;            // [warp8][ks8][lane32][4]
    uint32_t* KF = sh + 8192;     // [na8][ks8][lane32][2]
    uint32_t* VF = sh + 12288;    // [na8][kt4][lane32][2] bf16x2

    int tid = threadIdx.x, lane = tid & 31, wid = tid >> 5;
    int g = lane >> 2, T = lane & 3;
    int bh = blockIdx.y, b_ = bh / HH, h_ = bh % HH;
    int q0 = blockIdx.x * 128;
    size_t baseTok = (size_t)b_ * SS;

    int cg = tid & 15, ksq = cg >> 1, hfq = cg & 1;
    int sw = ksq & 3;
    int p0 = ((0 ^ sw) << 1), p1 = ((1 ^ sw) << 1),
        p2 = ((2 ^ sw) << 1), p3 = ((3 ^ sw) << 1);

    // ---- stage Q (pre-scaled by 1/8; qkv already tf32) ----
    #pragma unroll
    for (int i = 0; i < 8; i++) {
        int r = (tid >> 4) + i * 16;
        int wf = r >> 4, row = r & 15;
        int d = ((wf * 8 + ksq) * 32 + (row & 7) * 4) * 4 + (row >> 3) + 2 * hfq;
        float4 v = *(const float4*)(qkv + (baseTok + q0 + r) * NQKV + h_ * 64 + cg * 4);
        QF[d + (p0<<1)] = __float_as_uint(v.x * 0.125f);
        QF[d + (p1<<1)] = __float_as_uint(v.y * 0.125f);
        QF[d + (p2<<1)] = __float_as_uint(v.z * 0.125f);
        QF[d + (p3<<1)] = __float_as_uint(v.w * 0.125f);
    }

    // K staging geometry (tf32 B-frag, as R9)
    int kD[4]; size_t kS[4];
    #pragma unroll
    for (int i = 0; i < 4; i++) {
        int key = (tid >> 4) + i * 16;
        kD[i] = (((key >> 3) * 8 + ksq) * 32 + (key & 7) * 4) * 2 + hfq;
        kS[i] = (baseTok + key) * NQKV + DD + h_ * 64 + cg * 4;
    }
    // V staging geometry (bf16 b-frag): thread -> (d, kt)
    int vd = tid >> 2, vkt = tid & 3;
    int vslot = (((vd >> 3) * 4 + vkt) * 32 + (vd & 7) * 4) * 2;   // + T*2 + delta
    const __nv_bfloat16* vrow = vt16 + ((size_t)bh * 64 + vd) * SS + vkt * 16;

    float oacc[8][4];
    #pragma unroll
    for (int na = 0; na < 8; na++)
        #pragma unroll
        for (int r = 0; r < 4; r++) oacc[na][r] = 0.0f;
    float m0 = -1e30f, m1 = -1e30f, l0 = 0.0f, l1 = 0.0f;

    // prefetch first K/V tile
    float4 kreg[4]; uint4 vreg[2];
    #pragma unroll
    for (int i = 0; i < 4; i++) kreg[i] = *(const float4*)(qkv + kS[i]);
    vreg[0] = *(const uint4*)(vrow);
    vreg[1] = *(const uint4*)(vrow + 8);

    for (int s0 = 0; s0 < SS; s0 += 64) {
        __syncthreads();   // prev-iter KF/VF readers done
        #pragma unroll
        for (int i = 0; i < 4; i++) {
            KF[kD[i]+p0] = __float_as_uint(kreg[i].x);
            KF[kD[i]+p1] = __float_as_uint(kreg[i].y);
            KF[kD[i]+p2] = __float_as_uint(kreg[i].z);
            KF[kD[i]+p3] = __float_as_uint(kreg[i].w);
        }
        {
            const uint32_t* w1 = (const uint32_t*)&vreg[0];
            const uint32_t* w2 = (const uint32_t*)&vreg[1];
            #pragma unroll
            for (int Ti = 0; Ti < 4; Ti++)
                *(uint2*)&VF[vslot + Ti * 2] = make_uint2(w1[Ti], w2[Ti]);
        }
        __syncthreads();
        if (s0 + 64 < SS) {
            #pragma unroll
            for (int i = 0; i < 4; i++)
                kreg[i] = *(const float4*)(qkv + kS[i] + (size_t)(s0 + 64) * NQKV);
            vreg[0] = *(const uint4*)(vrow + s0 + 64);
            vreg[1] = *(const uint4*)(vrow + s0 + 72);
        }

        // S = Q @ K^T (tf32)
        float sacc[8][4];
        #pragma unroll
        for (int na = 0; na < 8; na++)
            #pragma unroll
            for (int r = 0; r < 4; r++) sacc[na][r] = 0.0f;
        #pragma unroll
        for (int ks = 0; ks < 8; ks++) {
            int lx = lane ^ (ks & 3);
            uint32_t qa[4];
            *(uint4*)qa = *(const uint4*)&QF[((wid * 8 + ks) * 32 + lx) * 4];
            #pragma unroll
            for (int na = 0; na < 8; na++) {
                uint32_t kb[2];
                *(uint2*)kb = *(const uint2*)&KF[((na * 8 + ks) * 32 + lx) * 2];
                mma8(sacc[na], qa, kb);
            }
        }

        // online softmax; pack P directly into bf16 A-fragments
        float rm0 = -1e30f, rm1 = -1e30f;
        #pragma unroll
        for (int na = 0; na < 8; na++) {
            rm0 = fmaxf(rm0, fmaxf(sacc[na][0], sacc[na][1]));
            rm1 = fmaxf(rm1, fmaxf(sacc[na][2], sacc[na][3]));
        }
        rm0 = fmaxf(rm0, __shfl_xor_sync(0xffffffffu, rm0, 1));
        rm0 = fmaxf(rm0, __shfl_xor_sync(0xffffffffu, rm0, 2));
        rm1 = fmaxf(rm1, __shfl_xor_sync(0xffffffffu, rm1, 1));
        rm1 = fmaxf(rm1, __shfl_xor_sync(0xffffffffu, rm1, 2));
        float mn0 = fmaxf(m0, rm0), mn1 = fmaxf(m1, rm1);
        float al0 = __expf(m0 - mn0), al1 = __expf(m1 - mn1);
        m0 = mn0; m1 = mn1;
        float rs0 = 0.0f, rs1 = 0.0f;
        uint32_t pregs[4][4];
        #pragma unroll
        for (int na = 0; na < 8; na++) {
            float e0 = __expf(sacc[na][0] - mn0);
            float e1 = __expf(sacc[na][1] - mn0);
            float e2 = __expf(sacc[na][2] - mn1);
            float e3 = __expf(sacc[na][3] - mn1);
            rs0 += e0 + e1; rs1 += e2 + e3;
            int kt = na >> 1;
            if ((na & 1) == 0) {
                pregs[kt][0] = packbf(e0, e1);   // row g,   cols 2T,2T+1
                pregs[kt][1] = packbf(e2, e3);   // row g+8
            } else {
                pregs[kt][2] = packbf(e0, e1);   // row g,   cols 2T+8,2T+9
                pregs[kt][3] = packbf(e2, e3);   // row g+8
            }
        }
        rs0 += __shfl_xor_sync(0xffffffffu, rs0, 1);
        rs0 += __shfl_xor_sync(0xffffffffu, rs0, 2);
        rs1 += __shfl_xor_sync(0xffffffffu, rs1, 1);
        rs1 += __shfl_xor_sync(0xffffffffu, rs1, 2);
        l0 = l0 * al0 + rs0; l1 = l1 * al1 + rs1;
        #pragma unroll
        for (int na = 0; na < 8; na++) {
            oacc[na][0] *= al0; oacc[na][1] *= al0;
            oacc[na][2] *= al1; oacc[na][3] *= al1;
        }

        // O += P @ V (bf16 m16n8k16)
        #pragma unroll
        for (int kt = 0; kt < 4; kt++) {
            #pragma unroll
            for (int na = 0; na < 8; na++) {
                uint32_t vb[2];
                *(uint2*)vb = *(const uint2*)&VF[((na * 4 + kt) * 32 + lane) * 2];
                mma16bf(oacc[na], pregs[kt], vb);
            }
        }
    }

    // epilogue (tf32-rounded: feeds O-proj GEMM)
    float inv0 = 1.0f / l0, inv1 = 1.0f / l1;
    int row0 = q0 + wid * 16 + g;
    #pragma unroll
    for (int na = 0; na < 8; na++) {
        int col = h_ * 64 + na * 8 + 2 * T;
        *(float2*)(o + (baseTok + row0)     * DD + col) =
            make_float2(f2tff(oacc[na][0] * inv0), f2tff(oacc[na][1] * inv0));
        *(float2*)(o + (baseTok + row0 + 8) * DD + col) =
            make_float2(f2tff(oacc[na][2] * inv1), f2tff(oacc[na][3] * inv1));
    }
}

// ---------------- launch ---------------------------------------------------
extern "C" void kernel_launch(void* const* d_in, const int* in_sizes, int n_in,
                              void* d_out, int out_size)
{
    (void)in_sizes; (void)n_in; (void)out_size;
    const float* x    = (const float*)d_in[0];
    const float* wq_w = (const float*)d_in[1];
    const float* wq_b = (const float*)d_in[2];
    const float* wk_w = (const float*)d_in[3];
    const float* wk_b = (const float*)d_in[4];
    const float* wv_w = (const float*)d_in[5];
    const float* wv_b = (const float*)d_in[6];
    const float* wo_w = (const float*)d_in[7];
    const float* wo_b = (const float*)d_in[8];
    const float* ln_g = (const float*)d_in[9];
    const float* ln_b = (const float*)d_in[10];
    const float* w1   = (const float*)d_in[11];
    const float* b1   = (const float*)d_in[12];
    const float* w2   = (const float*)d_in[13];
    const float* b2   = (const float*)d_in[14];
    float* out = (float*)d_out;

    float *h, *qkv, *o, *y, *z, *u, *wtq, *btq, *wto, *wt1, *wt2;
    __nv_bfloat16* vt16;
    cudaGetSymbolAddress((void**)&h,    g_h);
    cudaGetSymbolAddress((void**)&qkv,  g_qkv);
    cudaGetSymbolAddress((void**)&vt16, g_vt16);
    cudaGetSymbolAddress((void**)&o,    g_o);
    cudaGetSymbolAddress((void**)&y,    g_y);
    cudaGetSymbolAddress((void**)&z,    g_z);
    cudaGetSymbolAddress((void**)&u,    g_u);
    cudaGetSymbolAddress((void**)&wtq,  g_wtq);
    cudaGetSymbolAddress((void**)&btq,  g_btq);
    cudaGetSymbolAddress((void**)&wto,  g_wto);
    cudaGetSymbolAddress((void**)&wt1,  g_wt1);
    cudaGetSymbolAddress((void**)&wt2,  g_wt2);

    cudaFuncSetAttribute(tc_gemm<false, false, true >, cudaFuncAttributeMaxDynamicSharedMemorySize, GEMM_SMEM);
    cudaFuncSetAttribute(tc_gemm<false, true,  false>, cudaFuncAttributeMaxDynamicSharedMemorySize, GEMM_SMEM);
    cudaFuncSetAttribute(tc_gemm<true,  false, true >, cudaFuncAttributeMaxDynamicSharedMemorySize, GEMM_SMEM);
    cudaFuncSetAttribute(attn_kernel, cudaFuncAttributeMaxDynamicSharedMemorySize, ATTN_SMEM);

    // 0) prep (weights + bias + LN1 fused; launch idx 0)
    prep_kernel<<<6913 + MM, dim3(32, 8)>>>(wq_w, wk_w, wv_w, wq_b, wk_b, wv_b,
                                            wo_w, w1, w2, x, ln_g, ln_b,
                                            wtq, btq, wto, wt1, wt2, h);

    // 1) fused QKV projection (tf32 out)
    tc_gemm<false, false, true><<<dim3(NQKV/128, MM/128), 256, GEMM_SMEM>>>(h, wtq, btq, nullptr, qkv, NQKV, DD);

    // 2) V transpose+bf16 pack
    vtrans_kernel<<<dim3(SS/32, 2, BB*HH), dim3(32, 8)>>>(qkv, vt16);

    // 3) attention  (launch idx 3 -> ncu capture slot)
    attn_kernel<<<dim3(SS/128, BB*HH), 256, ATTN_SMEM>>>(qkv, vt16, o);

    // 4) O-proj + bias + residual(x) -> fp32 y
    tc_gemm<false, true, false><<<dim3(DD/128, MM/128), 256, GEMM_SMEM>>>(o, wto, wo_b, x, y, DD, DD);

    // 5) LN2 (tf32 out)
    ln_kernel<<<MM, 256>>>(y, ln_g, ln_b, z);

    // 6) FFN1 + bias + exact GELU (tf32 out)
    tc_gemm<true, false, true><<<dim3(FF/128, MM/128), 256, GEMM_SMEM>>>(z, wt1, b1, nullptr, u, FF, DD);

    // 7) FFN2 + bias + residual(y) -> out (fp32)
    tc_gemm<false, true, false><<<dim3(DD/128, MM/128), 256, GEMM_SMEM>>>(u, wt2, b2, y, out, DD, FF);
}